// round 12
// baseline (speedup 1.0000x reference)
#include <cuda_runtime.h>
#include <stdint.h>

#define NN 2048
#define NW 64    // 2048 bits = 64 u32 words
#define CAP 128  // CSC capacity per column of A_pos
#define NTHR 256

// ---------------- device scratch ----------------
__device__ __align__(16) uint32_t g_apT[NN*NW];
__device__ unsigned short g_idx[NN*CAP];
__device__ int      g_cnt[NN];
__device__ __align__(16) uint32_t g_lastT[6][NN*NW];
__device__ __align__(16) uint32_t g_U[6][NN*NW];     // union bits per stage
__device__ int      g_pc[6*NN];
__device__ float    g_cs[6*256];
__device__ unsigned short g_list[6][NN*1024];        // per-row index lists (set or complement)
__device__ int      g_llen[6][NN];                   // len | (comp<<16)
__device__ __align__(16) float g_h1[NN*256];
__device__ __align__(16) float g_t1[NN*256];         // dinv0 .* h1
__device__ __align__(16) float g_xb[5][NN*64];       // h2, h3, x3, x4, x5
__device__ __align__(16) float g_tb[5][NN*64];       // t2..t6
__device__ volatile int g_arrive[512];               // per-block arrival flags (monotonic)
__device__ volatile int g_barGen = 0;                // barrier generation (monotonic)

// ---------------- contention-free software grid barrier ----------------
// Arrival: each block stores gen+1 into its own slot (no atomics).
// Block 0's threads poll all slots in parallel, then publish the new generation.
__device__ __forceinline__ void gsync()
{
    __threadfence();
    __syncthreads();
    int gen = g_barGen;
    if (threadIdx.x == 0)
        g_arrive[blockIdx.x] = gen + 1;
    if (blockIdx.x == 0) {
        for (int b = threadIdx.x; b < (int)gridDim.x; b += blockDim.x)
            while (g_arrive[b] < gen + 1) { __nanosleep(32); }
        __syncthreads();
        __threadfence();
        if (threadIdx.x == 0) g_barGen = gen + 1;
    } else {
        if (threadIdx.x == 0)
            while (g_barGen < gen + 1) { __nanosleep(32); }
    }
    __syncthreads();
}

// ---------------- pack: [0,512) A_pos -> apT+CSC ; [512,1024) A_neg -> U0,lastT0,pc0 ----------------
__device__ void pack_unit(int u, const float* __restrict__ Apos, const float* __restrict__ Aneg, int tid)
{
    int lane = tid & 31;
    if (u < 512) {
        int gwarp = u*8 + (tid >> 5);
        int ti = gwarp >> 6, tj = gwarp & 63;
        uint32_t tbits = 0;
#pragma unroll
        for (int r = 0; r < 32; r++) {
            float v = Apos[(size_t)(ti*32 + r)*NN + tj*32 + lane];
            tbits |= (v > 0.f ? 1u : 0u) << r;
        }
        int j = tj*32 + lane;
        g_apT[j*NW + ti] = tbits;
        uint32_t m = tbits;
        while (m) {
            int r = __ffs(m) - 1; m &= (m-1);
            int pos = atomicAdd(&g_cnt[j], 1);
            if (pos < CAP) g_idx[j*CAP + pos] = (unsigned short)(ti*32 + r);
        }
    } else {
        int gwarp = (u - 512)*8 + (tid >> 5);
        int ti = gwarp >> 6, tj = gwarp & 63;
        uint32_t tbits = 0, rw = 0;
#pragma unroll
        for (int r = 0; r < 32; r++) {
            float v = Aneg[(size_t)(ti*32 + r)*NN + tj*32 + lane];
            uint32_t b = (v > 0.f) ? 1u : 0u;
            tbits |= b << r;
            uint32_t m = __ballot_sync(0xffffffffu, b);
            if (lane == r) rw = m;
        }
        g_U[0][(ti*32 + lane)*NW + tj] = rw;
        atomicAdd(&g_pc[ti*32 + lane], __popc(rw));
        g_lastT[0][(tj*32 + lane)*NW + ti] = tbits;
    }
}

// ---------------- bit stage: CSC expand + transpose + OR + pc ----------------
__device__ void bitstage_unit(int v, const uint4* __restrict__ lastOld4, uint4* __restrict__ lastNew4,
                              const uint32_t* __restrict__ uPrev, uint32_t* __restrict__ uCur,
                              int* __restrict__ pcCur, int tid, float* smemf)
{
    uint32_t (*sN)[33] = (uint32_t(*)[33])smemf;
    __syncthreads();
    int jt = v & 63, wt = v >> 6;
    int jl = tid >> 3, w4l = tid & 7;
    int j = jt*32 + jl;
    int w4 = wt*8 + w4l;

    int c = g_cnt[j]; if (c > CAP) c = CAP;
    const unsigned short* lst = g_idx + j*CAP;
    uint4 acc = make_uint4(0u,0u,0u,0u);
    int t = 0;
    for (; t + 4 <= c; t += 4) {
        int k0 = lst[t], k1 = lst[t+1], k2 = lst[t+2], k3 = lst[t+3];
        uint4 v0 = lastOld4[k0*16 + w4];
        uint4 v1 = lastOld4[k1*16 + w4];
        uint4 v2 = lastOld4[k2*16 + w4];
        uint4 v3 = lastOld4[k3*16 + w4];
        acc.x |= v0.x | v1.x | v2.x | v3.x;
        acc.y |= v0.y | v1.y | v2.y | v3.y;
        acc.z |= v0.z | v1.z | v2.z | v3.z;
        acc.w |= v0.w | v1.w | v2.w | v3.w;
    }
    for (; t < c; t++) {
        uint4 vv = lastOld4[lst[t]*16 + w4];
        acc.x |= vv.x; acc.y |= vv.y; acc.z |= vv.z; acc.w |= vv.w;
    }
    lastNew4[j*16 + w4] = acc;
    sN[jl][w4l*4 + 0] = acc.x;
    sN[jl][w4l*4 + 1] = acc.y;
    sN[jl][w4l*4 + 2] = acc.z;
    sN[jl][w4l*4 + 3] = acc.w;
    __syncthreads();

    int warp = tid >> 5, lane = tid & 31;
    for (int wl = warp; wl < 32; wl += 8) {
        uint32_t v2 = sN[lane][wl];
        uint32_t ow = 0;
#pragma unroll
        for (int ib = 0; ib < 32; ib++) {
            uint32_t mm = __ballot_sync(0xffffffffu, (v2 >> ib) & 1u);
            if (lane == ib) ow = mm;
        }
        int i = (wt*32 + wl)*32 + lane;
        uint32_t merged = uPrev[i*NW + jt] | ow;
        uCur[i*NW + jt] = merged;
        atomicAdd(&pcCur[i], __popc(merged));
    }
}

// ---------------- list build: per-row set-bit (or complement) index list ----------------
__device__ void list_unit(int u, const uint32_t* __restrict__ U, const int* __restrict__ pcS,
                          unsigned short* __restrict__ list, int* __restrict__ llen, int tid)
{
    int warp = tid >> 5, lane = tid & 31;
    for (int rr = 0; rr < 8; rr++) {
        int row = u*64 + warp*8 + rr;
        int pcv = pcS[row];
        bool comp = pcv > 1024;
        uint32_t m0 = U[row*NW + 2*lane];
        uint32_t m1 = U[row*NW + 2*lane + 1];
        if (comp) { m0 = ~m0; m1 = ~m1; }
        int cnt = __popc(m0) + __popc(m1);
        int incl = cnt;
#pragma unroll
        for (int off = 1; off < 32; off <<= 1) {
            int n = __shfl_up_sync(0xffffffffu, incl, off);
            if (lane >= off) incl += n;
        }
        int base = incl - cnt;
        unsigned short* dst = list + (size_t)row*1024 + base;
        int kb = lane*64;
        while (m0) { int b = __ffs(m0)-1; m0 &= (m0-1); *dst++ = (unsigned short)(kb + b); }
        kb += 32;
        while (m1) { int b = __ffs(m1)-1; m1 &= (m1-1); *dst++ = (unsigned short)(kb + b); }
        int total = __shfl_sync(0xffffffffu, incl, 31);
        if (lane == 31) llen[row] = total | (comp ? (1 << 16) : 0);
    }
}

// ---------------- gemm1: h1 = x @ W_l1 + b_l1 (32x64 tile, K-chunk 32) ----------------
__device__ void gemm1_unit(int u, const float* __restrict__ A, const float* __restrict__ W,
                           const float* __restrict__ bias, int tid, float* smemf)
{
    float (*As)[34] = (float(*)[34])smemf;             // 32x34
    float (*Ws)[64] = (float(*)[64])(smemf + 1088);    // 32x64
    __syncthreads();
    int tx = tid & 15, ty = tid >> 4;
    int rowBase = (u >> 2)*32, colBase = (u & 3)*64;
    float acc[2][4] = {};
    int mA = tid >> 3, kq = (tid & 7)*4;
    int kkW = tid >> 4, cW = (tid & 15)*4;

    for (int k0 = 0; k0 < 512; k0 += 32) {
        float4 a4 = *(const float4*)(A + (size_t)(rowBase + mA)*512 + k0 + kq);
        As[kq+0][mA] = a4.x; As[kq+1][mA] = a4.y;
        As[kq+2][mA] = a4.z; As[kq+3][mA] = a4.w;
        *(float4*)&Ws[kkW][cW]      = *(const float4*)(W + (size_t)(k0 + kkW)*256 + colBase + cW);
        *(float4*)&Ws[kkW+16][cW]   = *(const float4*)(W + (size_t)(k0 + kkW + 16)*256 + colBase + cW);
        __syncthreads();
#pragma unroll
        for (int kk = 0; kk < 32; kk++) {
            float2 av = *(const float2*)&As[kk][ty*2];
            float4 bv = *(const float4*)&Ws[kk][tx*4];
            acc[0][0] += av.x*bv.x; acc[0][1] += av.x*bv.y;
            acc[0][2] += av.x*bv.z; acc[0][3] += av.x*bv.w;
            acc[1][0] += av.y*bv.x; acc[1][1] += av.y*bv.y;
            acc[1][2] += av.y*bv.z; acc[1][3] += av.y*bv.w;
        }
        __syncthreads();
    }
#pragma unroll
    for (int a = 0; a < 2; a++) {
        int row = rowBase + ty*2 + a;
#pragma unroll
        for (int b = 0; b < 4; b++) {
            int col = colBase + tx*4 + b;
            g_h1[(size_t)row*256 + col] = acc[a][b] + bias[col];
        }
    }
}

// ---------------- t1 = dinv0 .* h1 ; cs0 colsum.  unit u in [0,64): 32 rows ----------------
__device__ void tcs1_unit(int u, int tid, float* smemf)
{
    float (*red)[256] = (float(*)[256])smemf;
    __syncthreads();
    int col4 = (tid & 63)*4;
    int rgrp = tid >> 6;
    int row0 = u*32;
    float s0=0.f, s1=0.f, s2=0.f, s3=0.f;
#pragma unroll
    for (int p = 0; p < 8; p++) {
        int row = row0 + rgrp*8 + p;
        float di = rsqrtf((float)(g_pc[row] + 1));
        float4 hv = *(const float4*)(g_h1 + (size_t)row*256 + col4);
        float4 tv = make_float4(di*hv.x, di*hv.y, di*hv.z, di*hv.w);
        *(float4*)(g_t1 + (size_t)row*256 + col4) = tv;
        s0 += tv.x; s1 += tv.y; s2 += tv.z; s3 += tv.w;
    }
    red[rgrp][col4+0] = s0; red[rgrp][col4+1] = s1;
    red[rgrp][col4+2] = s2; red[rgrp][col4+3] = s3;
    __syncthreads();
    atomicAdd(&g_cs[tid], red[0][tid]+red[1][tid]+red[2][tid]+red[3][tid]);
}

// ---------------- agg1: unit u in [0,256): 8 rows ----------------
__device__ void agg1_unit(int u, const float* __restrict__ Wg, const float* __restrict__ bg,
                          const float* __restrict__ Wl, const float* __restrict__ bl,
                          int tid, float* smemf)
{
    float (*sZ)[256] = (float(*)[256])smemf;            // 2048
    float (*sX)[256] = (float(*)[256])(smemf + 2048);   // 2048
    float (*red)[64] = (float(*)[64])(smemf + 4096);    // 512
    __syncthreads();
    int row0 = u*8;

    // phase A: z = di*(S + t1_row), S from list0 over t1
    {
        int grp = tid >> 5, lane = tid & 31;
        int f = lane*8;
        int row = row0 + grp;
        int lv = g_llen[0][row];
        int len = lv & 0xFFFF;
        bool comp = (lv >> 16) != 0;
        const unsigned short* L = g_list[0] + (size_t)row*1024;
        float4 a0 = make_float4(0,0,0,0), a1 = make_float4(0,0,0,0);
        int t = 0;
        for (; t + 2 <= len; t += 2) {
            int k0 = L[t], k1 = L[t+1];
            float4 v00 = *(const float4*)(g_t1 + (size_t)k0*256 + f);
            float4 v01 = *(const float4*)(g_t1 + (size_t)k0*256 + f + 4);
            float4 v10 = *(const float4*)(g_t1 + (size_t)k1*256 + f);
            float4 v11 = *(const float4*)(g_t1 + (size_t)k1*256 + f + 4);
            a0.x += v00.x + v10.x; a0.y += v00.y + v10.y;
            a0.z += v00.z + v10.z; a0.w += v00.w + v10.w;
            a1.x += v01.x + v11.x; a1.y += v01.y + v11.y;
            a1.z += v01.z + v11.z; a1.w += v01.w + v11.w;
        }
        for (; t < len; t++) {
            int k0 = L[t];
            float4 v00 = *(const float4*)(g_t1 + (size_t)k0*256 + f);
            float4 v01 = *(const float4*)(g_t1 + (size_t)k0*256 + f + 4);
            a0.x += v00.x; a0.y += v00.y; a0.z += v00.z; a0.w += v00.w;
            a1.x += v01.x; a1.y += v01.y; a1.z += v01.z; a1.w += v01.w;
        }
        if (comp) {
            float4 c0 = *(const float4*)(g_cs + f);
            float4 c1 = *(const float4*)(g_cs + f + 4);
            a0.x = c0.x - a0.x; a0.y = c0.y - a0.y; a0.z = c0.z - a0.z; a0.w = c0.w - a0.w;
            a1.x = c1.x - a1.x; a1.y = c1.y - a1.y; a1.z = c1.z - a1.z; a1.w = c1.w - a1.w;
        }
        float di = rsqrtf((float)(g_pc[row] + 1));
        float4 t0 = *(const float4*)(g_t1 + (size_t)row*256 + f);
        float4 t1v = *(const float4*)(g_t1 + (size_t)row*256 + f + 4);
        sZ[grp][f+0] = di*(a0.x + t0.x); sZ[grp][f+1] = di*(a0.y + t0.y);
        sZ[grp][f+2] = di*(a0.z + t0.z); sZ[grp][f+3] = di*(a0.w + t0.w);
        sZ[grp][f+4] = di*(a1.x + t1v.x); sZ[grp][f+5] = di*(a1.y + t1v.y);
        sZ[grp][f+6] = di*(a1.z + t1v.z); sZ[grp][f+7] = di*(a1.w + t1v.w);
    }
    __syncthreads();

    // phase B: x1 = h1 + relu(z @ Wg + bg)
    {
        int col = tid;
        float a8[8] = {0,0,0,0,0,0,0,0};
        for (int k = 0; k < 256; k += 4) {
            float w0 = Wg[(size_t)(k+0)*256 + col];
            float w1 = Wg[(size_t)(k+1)*256 + col];
            float w2 = Wg[(size_t)(k+2)*256 + col];
            float w3 = Wg[(size_t)(k+3)*256 + col];
#pragma unroll
            for (int r = 0; r < 8; r++) {
                float4 zq = *(const float4*)&sZ[r][k];
                a8[r] += zq.x*w0 + zq.y*w1 + zq.z*w2 + zq.w*w3;
            }
        }
        float bv = bg[col];
#pragma unroll
        for (int r = 0; r < 8; r++)
            sX[r][col] = g_h1[(size_t)(row0 + r)*256 + col] + fmaxf(a8[r] + bv, 0.f);
    }
    __syncthreads();

    // phase C: h2 = x1 @ W_l2 + b_l2; t2 = dinv1*h2; cs1
    {
        int col = tid & 63;
        int rg = tid >> 6;
        float v0 = 0.f, v1 = 0.f;
        if (col < 62) {
            for (int k = 0; k < 256; k += 4) {
                float w0 = Wl[(size_t)(k+0)*62 + col];
                float w1 = Wl[(size_t)(k+1)*62 + col];
                float w2 = Wl[(size_t)(k+2)*62 + col];
                float w3 = Wl[(size_t)(k+3)*62 + col];
                float4 xa = *(const float4*)&sX[rg*2][k];
                float4 xb = *(const float4*)&sX[rg*2+1][k];
                v0 += xa.x*w0 + xa.y*w1 + xa.z*w2 + xa.w*w3;
                v1 += xb.x*w0 + xb.y*w1 + xb.z*w2 + xb.w*w3;
            }
            float bv = bl[col];
            v0 += bv; v1 += bv;
        }
        int rA = row0 + rg*2, rB = rA + 1;
        float dA = rsqrtf((float)(g_pc[NN + rA] + 1));
        float dB = rsqrtf((float)(g_pc[NN + rB] + 1));
        g_xb[0][(size_t)rA*64 + col] = v0;
        g_xb[0][(size_t)rB*64 + col] = v1;
        float tA = dA*v0, tB = dB*v1;
        g_tb[0][(size_t)rA*64 + col] = tA;
        g_tb[0][(size_t)rB*64 + col] = tB;
        red[rg*2][col] = tA;
        red[rg*2+1][col] = tB;
    }
    __syncthreads();
    if (tid < 64) {
        float s = 0.f;
#pragma unroll
        for (int r = 0; r < 8; r++) s += red[r][tid];
        atomicAdd(&g_cs[256 + tid], s);
    }
}

// ---------------- agg64: unit u in [0,128): 16 rows ----------------
__device__ void agg64_unit(int u,
        const float* __restrict__ h, const float* __restrict__ tArr, int NcIn,
        const float* __restrict__ Wg, int ldwg, const float* __restrict__ bg,
        const int* __restrict__ pcS,
        const unsigned short* __restrict__ lst, const int* __restrict__ llen,
        const float* __restrict__ cs,
        float wscale, int doRelu,
        const float* __restrict__ Wl, const float* __restrict__ bl,
        const int* __restrict__ pcNext, float* __restrict__ tNext, float* __restrict__ csNext,
        float* __restrict__ outp, int tid, float* smemf)
{
    float (*sW)[64] = (float(*)[64])smemf;            // 4096
    float (*sZ)[64] = (float(*)[64])(smemf + 4096);   // 1024
    float (*red)[64] = (float(*)[64])(smemf + 5120);  // 1024
    __syncthreads();
    int row0 = u*16;

    for (int t = tid; t < 64*64; t += NTHR) {
        int k = t >> 6, c = t & 63;
        sW[k][c] = (k < NcIn && c < NcIn) ? Wg[(size_t)k*ldwg + c] : 0.f;
    }

    // phase A
    {
        int grp = tid >> 4, lane = tid & 15;
        int f = lane*4;
        int row = row0 + grp;
        int lv = llen[row];
        int len = lv & 0xFFFF;
        bool comp = (lv >> 16) != 0;
        const unsigned short* L = lst + (size_t)row*1024;
        float4 acc = make_float4(0,0,0,0);
        int t = 0;
        for (; t + 4 <= len; t += 4) {
            ushort4 k4 = *(const ushort4*)(L + t);
            float4 a = *(const float4*)(tArr + (size_t)k4.x*64 + f);
            float4 b = *(const float4*)(tArr + (size_t)k4.y*64 + f);
            float4 c2 = *(const float4*)(tArr + (size_t)k4.z*64 + f);
            float4 d = *(const float4*)(tArr + (size_t)k4.w*64 + f);
            acc.x += (a.x + b.x) + (c2.x + d.x);
            acc.y += (a.y + b.y) + (c2.y + d.y);
            acc.z += (a.z + b.z) + (c2.z + d.z);
            acc.w += (a.w + b.w) + (c2.w + d.w);
        }
        for (; t < len; t++) {
            float4 a = *(const float4*)(tArr + (size_t)L[t]*64 + f);
            acc.x += a.x; acc.y += a.y; acc.z += a.z; acc.w += a.w;
        }
        if (comp) {
            float4 c4 = *(const float4*)(cs + f);
            acc.x = c4.x - acc.x; acc.y = c4.y - acc.y;
            acc.z = c4.z - acc.z; acc.w = c4.w - acc.w;
        }
        float di = rsqrtf((float)(pcS[row] + 1));
        float4 tr = *(const float4*)(tArr + (size_t)row*64 + f);
        sZ[grp][f+0] = di*(acc.x + tr.x);
        sZ[grp][f+1] = di*(acc.y + tr.y);
        sZ[grp][f+2] = di*(acc.z + tr.z);
        sZ[grp][f+3] = di*(acc.w + tr.w);
    }
    __syncthreads();

    // phase B: y = h + wscale*act(z@Wg + bg)
    int r = tid >> 4;
    int c = (tid & 15)*4;
    int row = row0 + r;
    float y[4] = {0.f, 0.f, 0.f, 0.f};
#pragma unroll 8
    for (int k = 0; k < 64; k++) {
        float zv = sZ[r][k];
        y[0] += zv*sW[k][c+0];
        y[1] += zv*sW[k][c+1];
        y[2] += zv*sW[k][c+2];
        y[3] += zv*sW[k][c+3];
    }
#pragma unroll
    for (int j = 0; j < 4; j++) {
        int cc = c + j;
        float b = (cc < NcIn) ? bg[cc] : 0.f;
        float v = y[j] + b;
        if (doRelu) v = fmaxf(v, 0.f);
        y[j] = h[(size_t)row*64 + cc] + wscale*v;
    }

    float val[4];
    if (Wl) {
        __syncthreads();
#pragma unroll
        for (int j = 0; j < 4; j++) sZ[r][c+j] = y[j];
        for (int t = tid; t < 64*64; t += NTHR) {
            int k = t >> 6, cc2 = t & 63;
            sW[k][cc2] = (k < NcIn) ? Wl[(size_t)k*64 + cc2] : 0.f;
        }
        __syncthreads();
#pragma unroll
        for (int j = 0; j < 4; j++) val[j] = 0.f;
#pragma unroll 8
        for (int k = 0; k < 64; k++) {
            float yv = sZ[r][k];
            val[0] += yv*sW[k][c+0];
            val[1] += yv*sW[k][c+1];
            val[2] += yv*sW[k][c+2];
            val[3] += yv*sW[k][c+3];
        }
#pragma unroll
        for (int j = 0; j < 4; j++) val[j] += bl[c+j];
    } else {
#pragma unroll
        for (int j = 0; j < 4; j++) val[j] = y[j];
    }

#pragma unroll
    for (int j = 0; j < 4; j++) outp[(size_t)row*64 + c + j] = val[j];

    if (csNext) {
        float dN = rsqrtf((float)(pcNext[row] + 1));
        __syncthreads();
#pragma unroll
        for (int j = 0; j < 4; j++) {
            float tv = dN*val[j];
            tNext[(size_t)row*64 + c + j] = tv;
            red[r][c+j] = tv;
        }
        __syncthreads();
        if (tid < 64) {
            float s = 0.f;
#pragma unroll
            for (int rr = 0; rr < 16; rr++) s += red[rr][tid];
            atomicAdd(&csNext[tid], s);
        }
    }
}

// ---------------- the mega kernel ----------------
__global__ void __launch_bounds__(NTHR, 2) mega_kernel(
        const float* __restrict__ x, const float* __restrict__ Aneg, const float* __restrict__ Apos,
        const float* __restrict__ W_l1, const float* __restrict__ b_l1,
        const float* __restrict__ W_l2, const float* __restrict__ b_l2,
        const float* __restrict__ W_l3, const float* __restrict__ b_l3,
        const float* __restrict__ W_g1, const float* __restrict__ b_g1,
        const float* __restrict__ W_g2, const float* __restrict__ b_g2,
        const float* __restrict__ W_g3, const float* __restrict__ b_g3,
        const float* __restrict__ W_g4, const float* __restrict__ b_g4,
        const float* __restrict__ W_g5, const float* __restrict__ b_g5,
        const float* __restrict__ W_g6, const float* __restrict__ b_g6,
        float* __restrict__ out)
{
    __shared__ __align__(16) float smemf[6144];   // 24 KB
    int tid = threadIdx.x;
    int nb = gridDim.x;

    // P0: zero
    for (int i = blockIdx.x*NTHR + tid; i < 6*NN;  i += nb*NTHR) g_pc[i] = 0;
    for (int i = blockIdx.x*NTHR + tid; i < 6*256; i += nb*NTHR) g_cs[i] = 0.f;
    for (int i = blockIdx.x*NTHR + tid; i < NN;    i += nb*NTHR) g_cnt[i] = 0;
    gsync();

    // P1: pack (1024) + gemm1 (256)
    for (int u = blockIdx.x; u < 1280; u += nb) {
        if (u < 1024) pack_unit(u, Apos, Aneg, tid);
        else gemm1_unit(u - 1024, x, W_l1, b_l1, tid, smemf);
    }
    gsync();

    // P2: tcs1 (64) + bitstage1 (128) + list0 (32)
    for (int u = blockIdx.x; u < 224; u += nb) {
        if (u < 64) tcs1_unit(u, tid, smemf);
        else if (u < 192) bitstage_unit(u - 64, (const uint4*)g_lastT[0], (uint4*)g_lastT[1],
                                        g_U[0], g_U[1], g_pc + NN, tid, smemf);
        else list_unit(u - 192, g_U[0], g_pc, g_list[0], g_llen[0], tid);
    }
    gsync();

    // P3: agg1 (256) + bitstage2 (128) + list1 (32)
    for (int u = blockIdx.x; u < 416; u += nb) {
        if (u < 256) agg1_unit(u, W_g1, b_g1, W_l2, b_l2, tid, smemf);
        else if (u < 384) bitstage_unit(u - 256, (const uint4*)g_lastT[1], (uint4*)g_lastT[2],
                                        g_U[1], g_U[2], g_pc + 2*NN, tid, smemf);
        else list_unit(u - 384, g_U[1], g_pc + NN, g_list[1], g_llen[1], tid);
    }
    gsync();

    // P4: agg2 (128) + bitstage3 (128) + list2 (32)
    for (int u = blockIdx.x; u < 288; u += nb) {
        if (u < 128) agg64_unit(u, g_xb[0], g_tb[0], 62, W_g2, 62, b_g2,
                                g_pc + NN, g_list[1], g_llen[1], g_cs + 256,
                                1.0f, 1, W_l3, b_l3,
                                g_pc + 2*NN, g_tb[1], g_cs + 2*256,
                                g_xb[1], tid, smemf);
        else if (u < 256) bitstage_unit(u - 128, (const uint4*)g_lastT[2], (uint4*)g_lastT[3],
                                        g_U[2], g_U[3], g_pc + 3*NN, tid, smemf);
        else list_unit(u - 256, g_U[2], g_pc + 2*NN, g_list[2], g_llen[2], tid);
    }
    gsync();

    // P5: agg3 (128) + bitstage4 (128) + list3 (32)
    for (int u = blockIdx.x; u < 288; u += nb) {
        if (u < 128) agg64_unit(u, g_xb[1], g_tb[1], 64, W_g3, 64, b_g3,
                                g_pc + 2*NN, g_list[2], g_llen[2], g_cs + 2*256,
                                0.5f, 1, nullptr, nullptr,
                                g_pc + 3*NN, g_tb[2], g_cs + 3*256,
                                g_xb[2], tid, smemf);
        else if (u < 256) bitstage_unit(u - 128, (const uint4*)g_lastT[3], (uint4*)g_lastT[4],
                                        g_U[3], g_U[4], g_pc + 4*NN, tid, smemf);
        else list_unit(u - 256, g_U[3], g_pc + 3*NN, g_list[3], g_llen[3], tid);
    }
    gsync();

    // P6: agg4 (128) + bitstage5 (128) + list4 (32)
    for (int u = blockIdx.x; u < 288; u += nb) {
        if (u < 128) agg64_unit(u, g_xb[2], g_tb[2], 64, W_g4, 64, b_g4,
                                g_pc + 3*NN, g_list[3], g_llen[3], g_cs + 3*256,
                                0.5f, 1, nullptr, nullptr,
                                g_pc + 4*NN, g_tb[3], g_cs + 4*256,
                                g_xb[3], tid, smemf);
        else if (u < 256) bitstage_unit(u - 128, (const uint4*)g_lastT[4], (uint4*)g_lastT[5],
                                        g_U[4], g_U[5], g_pc + 5*NN, tid, smemf);
        else list_unit(u - 256, g_U[4], g_pc + 4*NN, g_list[4], g_llen[4], tid);
    }
    gsync();

    // P7: agg5 (128) + list5 (32)
    for (int u = blockIdx.x; u < 160; u += nb) {
        if (u < 128) agg64_unit(u, g_xb[3], g_tb[3], 64, W_g5, 64, b_g5,
                                g_pc + 4*NN, g_list[4], g_llen[4], g_cs + 4*256,
                                0.25f, 1, nullptr, nullptr,
                                g_pc + 5*NN, g_tb[4], g_cs + 5*256,
                                g_xb[4], tid, smemf);
        else list_unit(u - 128, g_U[5], g_pc + 5*NN, g_list[5], g_llen[5], tid);
    }
    gsync();

    // P8: agg6 (128, no relu) -> out
    for (int u = blockIdx.x; u < 128; u += nb)
        agg64_unit(u, g_xb[4], g_tb[4], 64, W_g6, 64, b_g6,
                   g_pc + 5*NN, g_list[5], g_llen[5], g_cs + 5*256,
                   0.25f, 0, nullptr, nullptr,
                   nullptr, nullptr, nullptr,
                   out, tid, smemf);
}

// ---------------- host ----------------
extern "C" void kernel_launch(void* const* d_in, const int* in_sizes, int n_in,
                              void* d_out, int out_size)
{
    const float* x    = (const float*)d_in[0];
    const float* Aneg = (const float*)d_in[1];
    const float* Apos = (const float*)d_in[2];
    const float* W_l1 = (const float*)d_in[3];  const float* b_l1 = (const float*)d_in[4];
    const float* W_l2 = (const float*)d_in[5];  const float* b_l2 = (const float*)d_in[6];
    const float* W_l3 = (const float*)d_in[7];  const float* b_l3 = (const float*)d_in[8];
    const float* W_g1 = (const float*)d_in[9];  const float* b_g1 = (const float*)d_in[10];
    const float* W_g2 = (const float*)d_in[11]; const float* b_g2 = (const float*)d_in[12];
    const float* W_g3 = (const float*)d_in[13]; const float* b_g3 = (const float*)d_in[14];
    const float* W_g4 = (const float*)d_in[15]; const float* b_g4 = (const float*)d_in[16];
    const float* W_g5 = (const float*)d_in[17]; const float* b_g5 = (const float*)d_in[18];
    const float* W_g6 = (const float*)d_in[19]; const float* b_g6 = (const float*)d_in[20];
    float* out = (float*)d_out;

    static int nblk = 0;
    if (!nblk) {
        int dev = 0, sms = 0, bpm = 0;
        cudaGetDevice(&dev);
        cudaDeviceGetAttribute(&sms, cudaDevAttrMultiProcessorCount, dev);
        cudaOccupancyMaxActiveBlocksPerMultiprocessor(&bpm, mega_kernel, NTHR, 0);
        if (sms <= 0) sms = 148;
        if (bpm <= 0) bpm = 2;
        if (bpm > 2) bpm = 2;
        nblk = sms * bpm;
        if (nblk > 512) nblk = 512;
    }

    mega_kernel<<<nblk, NTHR>>>(x, Aneg, Apos,
                                W_l1, b_l1, W_l2, b_l2, W_l3, b_l3,
                                W_g1, b_g1, W_g2, b_g2, W_g3, b_g3,
                                W_g4, b_g4, W_g5, b_g5, W_g6, b_g6,
                                out);
}

// round 13
// speedup vs baseline: 1.0506x; 1.0506x over previous
#include <cuda_runtime.h>
#include <stdint.h>

#define NN 2048
#define NW 64    // 2048 bits = 64 u32 words
#define CAP 128  // CSC capacity per column of A_pos
#define NTHR 256

// ---------------- device scratch ----------------
__device__ __align__(16) uint32_t g_apT[NN*NW];
__device__ unsigned short g_idx[NN*CAP];
__device__ int      g_cnt[NN];
__device__ __align__(16) uint32_t g_lastT[6][NN*NW];
__device__ __align__(16) uint32_t g_U[6][NN*NW];     // union bits per stage
__device__ int      g_pc[6*NN];
__device__ float    g_cs[6*256];
__device__ unsigned short g_list[6][NN*1024];        // per-row index lists (set or complement)
__device__ int      g_llen[6][NN];                   // len | (comp<<16)
__device__ __align__(16) float g_h1[NN*256];
__device__ __align__(16) float g_t1[NN*256];         // dinv0 .* h1
__device__ __align__(16) float g_xb[5][NN*64];       // h2, h3, x3, x4, x5
__device__ __align__(16) float g_tb[5][NN*64];       // t2..t6
__device__ int          g_barCount = 0;
__device__ volatile int g_barGen   = 0;

// ---------------- software grid barrier (atomic arrival — measured best) ----------------
__device__ __forceinline__ void gsync()
{
    __threadfence();
    __syncthreads();
    if (threadIdx.x == 0) {
        int gen = g_barGen;
        if (atomicAdd(&g_barCount, 1) == (int)gridDim.x - 1) {
            g_barCount = 0;
            __threadfence();
            g_barGen = gen + 1;
        } else {
            while (g_barGen == gen) { __nanosleep(32); }
        }
    }
    __syncthreads();
}

// ---------------- pack: [0,512) A_pos -> apT+CSC ; [512,1024) A_neg -> U0,lastT0,pc0 ----------------
__device__ void pack_unit(int u, const float* __restrict__ Apos, const float* __restrict__ Aneg, int tid)
{
    int lane = tid & 31;
    if (u < 512) {
        int gwarp = u*8 + (tid >> 5);
        int ti = gwarp >> 6, tj = gwarp & 63;
        uint32_t tbits = 0;
#pragma unroll
        for (int r = 0; r < 32; r++) {
            float v = Apos[(size_t)(ti*32 + r)*NN + tj*32 + lane];
            tbits |= (v > 0.f ? 1u : 0u) << r;
        }
        int j = tj*32 + lane;
        g_apT[j*NW + ti] = tbits;
        uint32_t m = tbits;
        while (m) {
            int r = __ffs(m) - 1; m &= (m-1);
            int pos = atomicAdd(&g_cnt[j], 1);
            if (pos < CAP) g_idx[j*CAP + pos] = (unsigned short)(ti*32 + r);
        }
    } else {
        int gwarp = (u - 512)*8 + (tid >> 5);
        int ti = gwarp >> 6, tj = gwarp & 63;
        uint32_t tbits = 0, rw = 0;
#pragma unroll
        for (int r = 0; r < 32; r++) {
            float v = Aneg[(size_t)(ti*32 + r)*NN + tj*32 + lane];
            uint32_t b = (v > 0.f) ? 1u : 0u;
            tbits |= b << r;
            uint32_t m = __ballot_sync(0xffffffffu, b);
            if (lane == r) rw = m;
        }
        g_U[0][(ti*32 + lane)*NW + tj] = rw;
        atomicAdd(&g_pc[ti*32 + lane], __popc(rw));
        g_lastT[0][(tj*32 + lane)*NW + ti] = tbits;
    }
}

// ---------------- bit stage: CSC expand + transpose + OR + pc ----------------
__device__ void bitstage_unit(int v, const uint4* __restrict__ lastOld4, uint4* __restrict__ lastNew4,
                              const uint32_t* __restrict__ uPrev, uint32_t* __restrict__ uCur,
                              int* __restrict__ pcCur, int tid, float* smemf)
{
    uint32_t (*sN)[33] = (uint32_t(*)[33])smemf;
    __syncthreads();
    int jt = v & 63, wt = v >> 6;
    int jl = tid >> 3, w4l = tid & 7;
    int j = jt*32 + jl;
    int w4 = wt*8 + w4l;

    int c = g_cnt[j]; if (c > CAP) c = CAP;
    const unsigned short* lst = g_idx + j*CAP;
    uint4 acc = make_uint4(0u,0u,0u,0u);
    int t = 0;
    for (; t + 4 <= c; t += 4) {
        int k0 = lst[t], k1 = lst[t+1], k2 = lst[t+2], k3 = lst[t+3];
        uint4 v0 = lastOld4[k0*16 + w4];
        uint4 v1 = lastOld4[k1*16 + w4];
        uint4 v2 = lastOld4[k2*16 + w4];
        uint4 v3 = lastOld4[k3*16 + w4];
        acc.x |= v0.x | v1.x | v2.x | v3.x;
        acc.y |= v0.y | v1.y | v2.y | v3.y;
        acc.z |= v0.z | v1.z | v2.z | v3.z;
        acc.w |= v0.w | v1.w | v2.w | v3.w;
    }
    for (; t < c; t++) {
        uint4 vv = lastOld4[lst[t]*16 + w4];
        acc.x |= vv.x; acc.y |= vv.y; acc.z |= vv.z; acc.w |= vv.w;
    }
    lastNew4[j*16 + w4] = acc;
    sN[jl][w4l*4 + 0] = acc.x;
    sN[jl][w4l*4 + 1] = acc.y;
    sN[jl][w4l*4 + 2] = acc.z;
    sN[jl][w4l*4 + 3] = acc.w;
    __syncthreads();

    int warp = tid >> 5, lane = tid & 31;
    for (int wl = warp; wl < 32; wl += 8) {
        uint32_t v2 = sN[lane][wl];
        uint32_t ow = 0;
#pragma unroll
        for (int ib = 0; ib < 32; ib++) {
            uint32_t mm = __ballot_sync(0xffffffffu, (v2 >> ib) & 1u);
            if (lane == ib) ow = mm;
        }
        int i = (wt*32 + wl)*32 + lane;
        uint32_t merged = uPrev[i*NW + jt] | ow;
        uCur[i*NW + jt] = merged;
        atomicAdd(&pcCur[i], __popc(merged));
    }
}

// ---------------- list build: per-row set-bit (or complement) index list ----------------
__device__ void list_unit(int u, const uint32_t* __restrict__ U, const int* __restrict__ pcS,
                          unsigned short* __restrict__ list, int* __restrict__ llen, int tid)
{
    int warp = tid >> 5, lane = tid & 31;
    for (int rr = 0; rr < 8; rr++) {
        int row = u*64 + warp*8 + rr;
        int pcv = pcS[row];
        bool comp = pcv > 1024;
        uint32_t m0 = U[row*NW + 2*lane];
        uint32_t m1 = U[row*NW + 2*lane + 1];
        if (comp) { m0 = ~m0; m1 = ~m1; }
        int cnt = __popc(m0) + __popc(m1);
        int incl = cnt;
#pragma unroll
        for (int off = 1; off < 32; off <<= 1) {
            int n = __shfl_up_sync(0xffffffffu, incl, off);
            if (lane >= off) incl += n;
        }
        int base = incl - cnt;
        unsigned short* dst = list + (size_t)row*1024 + base;
        int kb = lane*64;
        while (m0) { int b = __ffs(m0)-1; m0 &= (m0-1); *dst++ = (unsigned short)(kb + b); }
        kb += 32;
        while (m1) { int b = __ffs(m1)-1; m1 &= (m1-1); *dst++ = (unsigned short)(kb + b); }
        int total = __shfl_sync(0xffffffffu, incl, 31);
        if (lane == 31) llen[row] = total | (comp ? (1 << 16) : 0);
    }
}

// ---------------- gemm1: h1 = x @ W_l1 + b_l1 (32x64 tile, K-chunk 32) ----------------
__device__ void gemm1_unit(int u, const float* __restrict__ A, const float* __restrict__ W,
                           const float* __restrict__ bias, int tid, float* smemf)
{
    float (*As)[34] = (float(*)[34])smemf;             // 32x34
    float (*Ws)[64] = (float(*)[64])(smemf + 1088);    // 32x64
    __syncthreads();
    int tx = tid & 15, ty = tid >> 4;
    int rowBase = (u >> 2)*32, colBase = (u & 3)*64;
    float acc[2][4] = {};
    int mA = tid >> 3, kq = (tid & 7)*4;
    int kkW = tid >> 4, cW = (tid & 15)*4;

    for (int k0 = 0; k0 < 512; k0 += 32) {
        float4 a4 = *(const float4*)(A + (size_t)(rowBase + mA)*512 + k0 + kq);
        As[kq+0][mA] = a4.x; As[kq+1][mA] = a4.y;
        As[kq+2][mA] = a4.z; As[kq+3][mA] = a4.w;
        *(float4*)&Ws[kkW][cW]      = *(const float4*)(W + (size_t)(k0 + kkW)*256 + colBase + cW);
        *(float4*)&Ws[kkW+16][cW]   = *(const float4*)(W + (size_t)(k0 + kkW + 16)*256 + colBase + cW);
        __syncthreads();
#pragma unroll
        for (int kk = 0; kk < 32; kk++) {
            float2 av = *(const float2*)&As[kk][ty*2];
            float4 bv = *(const float4*)&Ws[kk][tx*4];
            acc[0][0] += av.x*bv.x; acc[0][1] += av.x*bv.y;
            acc[0][2] += av.x*bv.z; acc[0][3] += av.x*bv.w;
            acc[1][0] += av.y*bv.x; acc[1][1] += av.y*bv.y;
            acc[1][2] += av.y*bv.z; acc[1][3] += av.y*bv.w;
        }
        __syncthreads();
    }
#pragma unroll
    for (int a = 0; a < 2; a++) {
        int row = rowBase + ty*2 + a;
#pragma unroll
        for (int b = 0; b < 4; b++) {
            int col = colBase + tx*4 + b;
            g_h1[(size_t)row*256 + col] = acc[a][b] + bias[col];
        }
    }
}

// ---------------- t1 = dinv0 .* h1 ; cs0 colsum.  unit u in [0,64): 32 rows ----------------
__device__ void tcs1_unit(int u, int tid, float* smemf)
{
    float (*red)[256] = (float(*)[256])smemf;
    __syncthreads();
    int col4 = (tid & 63)*4;
    int rgrp = tid >> 6;
    int row0 = u*32;
    float s0=0.f, s1=0.f, s2=0.f, s3=0.f;
#pragma unroll
    for (int p = 0; p < 8; p++) {
        int row = row0 + rgrp*8 + p;
        float di = rsqrtf((float)(g_pc[row] + 1));
        float4 hv = *(const float4*)(g_h1 + (size_t)row*256 + col4);
        float4 tv = make_float4(di*hv.x, di*hv.y, di*hv.z, di*hv.w);
        *(float4*)(g_t1 + (size_t)row*256 + col4) = tv;
        s0 += tv.x; s1 += tv.y; s2 += tv.z; s3 += tv.w;
    }
    red[rgrp][col4+0] = s0; red[rgrp][col4+1] = s1;
    red[rgrp][col4+2] = s2; red[rgrp][col4+3] = s3;
    __syncthreads();
    atomicAdd(&g_cs[tid], red[0][tid]+red[1][tid]+red[2][tid]+red[3][tid]);
}

// ---------------- agg1: unit u in [0,256): 8 rows ----------------
__device__ void agg1_unit(int u, const float* __restrict__ Wg, const float* __restrict__ bg,
                          const float* __restrict__ Wl, const float* __restrict__ bl,
                          int tid, float* smemf)
{
    float (*sZ)[256] = (float(*)[256])smemf;            // 2048
    float (*sX)[256] = (float(*)[256])(smemf + 2048);   // 2048
    float (*red)[64] = (float(*)[64])(smemf + 4096);    // 512
    __syncthreads();
    int row0 = u*8;

    // phase A: z = di*(S + t1_row), S from list0 over t1
    {
        int grp = tid >> 5, lane = tid & 31;
        int f = lane*8;
        int row = row0 + grp;
        int lv = g_llen[0][row];
        int len = lv & 0xFFFF;
        bool comp = (lv >> 16) != 0;
        const unsigned short* L = g_list[0] + (size_t)row*1024;
        float4 a0 = make_float4(0,0,0,0), a1 = make_float4(0,0,0,0);
        int t = 0;
        for (; t + 2 <= len; t += 2) {
            int k0 = L[t], k1 = L[t+1];
            float4 v00 = *(const float4*)(g_t1 + (size_t)k0*256 + f);
            float4 v01 = *(const float4*)(g_t1 + (size_t)k0*256 + f + 4);
            float4 v10 = *(const float4*)(g_t1 + (size_t)k1*256 + f);
            float4 v11 = *(const float4*)(g_t1 + (size_t)k1*256 + f + 4);
            a0.x += v00.x + v10.x; a0.y += v00.y + v10.y;
            a0.z += v00.z + v10.z; a0.w += v00.w + v10.w;
            a1.x += v01.x + v11.x; a1.y += v01.y + v11.y;
            a1.z += v01.z + v11.z; a1.w += v01.w + v11.w;
        }
        for (; t < len; t++) {
            int k0 = L[t];
            float4 v00 = *(const float4*)(g_t1 + (size_t)k0*256 + f);
            float4 v01 = *(const float4*)(g_t1 + (size_t)k0*256 + f + 4);
            a0.x += v00.x; a0.y += v00.y; a0.z += v00.z; a0.w += v00.w;
            a1.x += v01.x; a1.y += v01.y; a1.z += v01.z; a1.w += v01.w;
        }
        if (comp) {
            float4 c0 = *(const float4*)(g_cs + f);
            float4 c1 = *(const float4*)(g_cs + f + 4);
            a0.x = c0.x - a0.x; a0.y = c0.y - a0.y; a0.z = c0.z - a0.z; a0.w = c0.w - a0.w;
            a1.x = c1.x - a1.x; a1.y = c1.y - a1.y; a1.z = c1.z - a1.z; a1.w = c1.w - a1.w;
        }
        float di = rsqrtf((float)(g_pc[row] + 1));
        float4 t0 = *(const float4*)(g_t1 + (size_t)row*256 + f);
        float4 t1v = *(const float4*)(g_t1 + (size_t)row*256 + f + 4);
        sZ[grp][f+0] = di*(a0.x + t0.x); sZ[grp][f+1] = di*(a0.y + t0.y);
        sZ[grp][f+2] = di*(a0.z + t0.z); sZ[grp][f+3] = di*(a0.w + t0.w);
        sZ[grp][f+4] = di*(a1.x + t1v.x); sZ[grp][f+5] = di*(a1.y + t1v.y);
        sZ[grp][f+6] = di*(a1.z + t1v.z); sZ[grp][f+7] = di*(a1.w + t1v.w);
    }
    __syncthreads();

    // phase B: x1 = h1 + relu(z @ Wg + bg)
    {
        int col = tid;
        float a8[8] = {0,0,0,0,0,0,0,0};
        for (int k = 0; k < 256; k += 4) {
            float w0 = Wg[(size_t)(k+0)*256 + col];
            float w1 = Wg[(size_t)(k+1)*256 + col];
            float w2 = Wg[(size_t)(k+2)*256 + col];
            float w3 = Wg[(size_t)(k+3)*256 + col];
#pragma unroll
            for (int r = 0; r < 8; r++) {
                float4 zq = *(const float4*)&sZ[r][k];
                a8[r] += zq.x*w0 + zq.y*w1 + zq.z*w2 + zq.w*w3;
            }
        }
        float bv = bg[col];
#pragma unroll
        for (int r = 0; r < 8; r++)
            sX[r][col] = g_h1[(size_t)(row0 + r)*256 + col] + fmaxf(a8[r] + bv, 0.f);
    }
    __syncthreads();

    // phase C: h2 = x1 @ W_l2 + b_l2; t2 = dinv1*h2; cs1
    {
        int col = tid & 63;
        int rg = tid >> 6;
        float v0 = 0.f, v1 = 0.f;
        if (col < 62) {
            for (int k = 0; k < 256; k += 4) {
                float w0 = Wl[(size_t)(k+0)*62 + col];
                float w1 = Wl[(size_t)(k+1)*62 + col];
                float w2 = Wl[(size_t)(k+2)*62 + col];
                float w3 = Wl[(size_t)(k+3)*62 + col];
                float4 xa = *(const float4*)&sX[rg*2][k];
                float4 xb = *(const float4*)&sX[rg*2+1][k];
                v0 += xa.x*w0 + xa.y*w1 + xa.z*w2 + xa.w*w3;
                v1 += xb.x*w0 + xb.y*w1 + xb.z*w2 + xb.w*w3;
            }
            float bv = bl[col];
            v0 += bv; v1 += bv;
        }
        int rA = row0 + rg*2, rB = rA + 1;
        float dA = rsqrtf((float)(g_pc[NN + rA] + 1));
        float dB = rsqrtf((float)(g_pc[NN + rB] + 1));
        g_xb[0][(size_t)rA*64 + col] = v0;
        g_xb[0][(size_t)rB*64 + col] = v1;
        float tA = dA*v0, tB = dB*v1;
        g_tb[0][(size_t)rA*64 + col] = tA;
        g_tb[0][(size_t)rB*64 + col] = tB;
        red[rg*2][col] = tA;
        red[rg*2+1][col] = tB;
    }
    __syncthreads();
    if (tid < 64) {
        float s = 0.f;
#pragma unroll
        for (int r = 0; r < 8; r++) s += red[r][tid];
        atomicAdd(&g_cs[256 + tid], s);
    }
}

// ---------------- agg64 v2: unit u in [0,512): 4 rows, 4 list-slices per row ----------------
__device__ void agg64_unit(int u,
        const float* __restrict__ h, const float* __restrict__ tArr, int NcIn,
        const float* __restrict__ Wg, int ldwg, const float* __restrict__ bg,
        const int* __restrict__ pcS,
        const unsigned short* __restrict__ lst, const int* __restrict__ llen,
        const float* __restrict__ cs,
        float wscale, int doRelu,
        const float* __restrict__ Wl, const float* __restrict__ bl,
        const int* __restrict__ pcNext, float* __restrict__ tNext, float* __restrict__ csNext,
        float* __restrict__ outp, int tid, float* smemf)
{
    float (*sW)[64]     = (float(*)[64])smemf;              // 64x64 = 4096
    float (*sZp)[4][64] = (float(*)[4][64])(smemf + 4096);  // 4x4x64 = 1024
    float (*sY)[64]     = (float(*)[64])(smemf + 5120);     // 4x64 = 256
    float (*red)[64]    = (float(*)[64])(smemf + 5376);     // 4x64 = 256
    __syncthreads();
    int row0 = u*4;

    for (int t = tid; t < 64*64; t += NTHR) {
        int k = t >> 6, c = t & 63;
        sW[k][c] = (k < NcIn && c < NcIn) ? Wg[(size_t)k*ldwg + c] : 0.f;
    }

    int r = tid >> 6;            // row within unit (0..3)
    int row = row0 + r;

    // phase A-1: slice partial sums.  64 threads/row = 4 slices x 16 lanes
    {
        int sl = (tid >> 4) & 3;
        int f = (tid & 15)*4;
        int lv = llen[row];
        int len = lv & 0xFFFF;
        const unsigned short* L = lst + (size_t)row*1024;
        int t0 = (len*sl) >> 2;
        int t1 = (len*(sl+1)) >> 2;
        float4 acc = make_float4(0,0,0,0);
        int t = t0;
        for (; t + 4 <= t1; t += 4) {
            int k0 = L[t], k1 = L[t+1], k2 = L[t+2], k3 = L[t+3];
            float4 a = *(const float4*)(tArr + (size_t)k0*64 + f);
            float4 b = *(const float4*)(tArr + (size_t)k1*64 + f);
            float4 c2 = *(const float4*)(tArr + (size_t)k2*64 + f);
            float4 d = *(const float4*)(tArr + (size_t)k3*64 + f);
            acc.x += (a.x + b.x) + (c2.x + d.x);
            acc.y += (a.y + b.y) + (c2.y + d.y);
            acc.z += (a.z + b.z) + (c2.z + d.z);
            acc.w += (a.w + b.w) + (c2.w + d.w);
        }
        for (; t < t1; t++) {
            float4 a = *(const float4*)(tArr + (size_t)L[t]*64 + f);
            acc.x += a.x; acc.y += a.y; acc.z += a.z; acc.w += a.w;
        }
        *(float4*)&sZp[r][sl][f] = acc;
    }
    __syncthreads();

    // phase A-2: combine slices + complement + dinv -> z (stored into sZp[r][0])
    int col = tid & 63;
    {
        float s = sZp[r][0][col] + sZp[r][1][col] + sZp[r][2][col] + sZp[r][3][col];
        bool comp = (llen[row] >> 16) != 0;
        if (comp) s = cs[col] - s;
        float di = rsqrtf((float)(pcS[row] + 1));
        float z = di*(s + tArr[(size_t)row*64 + col]);
        __syncthreads();
        sZp[r][0][col] = z;
    }
    __syncthreads();

    // phase B: y = h + wscale*act(z@Wg + bg), 1 output/thread
    float y = 0.f;
#pragma unroll 16
    for (int k = 0; k < 64; k++)
        y += sZp[r][0][k]*sW[k][col];
    {
        float b = (col < NcIn) ? bg[col] : 0.f;
        float v = y + b;
        if (doRelu) v = fmaxf(v, 0.f);
        y = h[(size_t)row*64 + col] + wscale*v;
    }

    float val;
    if (Wl) {
        sY[r][col] = y;
        __syncthreads();
        for (int t = tid; t < 64*64; t += NTHR) {
            int k = t >> 6, c2 = t & 63;
            sW[k][c2] = (k < NcIn) ? Wl[(size_t)k*64 + c2] : 0.f;
        }
        __syncthreads();
        val = 0.f;
#pragma unroll 16
        for (int k = 0; k < 64; k++)
            val += sY[r][k]*sW[k][col];
        val += bl[col];
    } else {
        val = y;
    }

    outp[(size_t)row*64 + col] = val;

    if (csNext) {
        float dN = rsqrtf((float)(pcNext[row] + 1));
        float tv = dN*val;
        tNext[(size_t)row*64 + col] = tv;
        red[r][col] = tv;
        __syncthreads();
        if (tid < 64)
            atomicAdd(&csNext[tid], red[0][tid]+red[1][tid]+red[2][tid]+red[3][tid]);
    }
}

// ---------------- the mega kernel ----------------
__global__ void __launch_bounds__(NTHR, 2) mega_kernel(
        const float* __restrict__ x, const float* __restrict__ Aneg, const float* __restrict__ Apos,
        const float* __restrict__ W_l1, const float* __restrict__ b_l1,
        const float* __restrict__ W_l2, const float* __restrict__ b_l2,
        const float* __restrict__ W_l3, const float* __restrict__ b_l3,
        const float* __restrict__ W_g1, const float* __restrict__ b_g1,
        const float* __restrict__ W_g2, const float* __restrict__ b_g2,
        const float* __restrict__ W_g3, const float* __restrict__ b_g3,
        const float* __restrict__ W_g4, const float* __restrict__ b_g4,
        const float* __restrict__ W_g5, const float* __restrict__ b_g5,
        const float* __restrict__ W_g6, const float* __restrict__ b_g6,
        float* __restrict__ out)
{
    __shared__ __align__(16) float smemf[6144];   // 24 KB
    int tid = threadIdx.x;
    int nb = gridDim.x;

    // P0: zero
    for (int i = blockIdx.x*NTHR + tid; i < 6*NN;  i += nb*NTHR) g_pc[i] = 0;
    for (int i = blockIdx.x*NTHR + tid; i < 6*256; i += nb*NTHR) g_cs[i] = 0.f;
    for (int i = blockIdx.x*NTHR + tid; i < NN;    i += nb*NTHR) g_cnt[i] = 0;
    gsync();

    // P1: pack (1024) + gemm1 (256)
    for (int u = blockIdx.x; u < 1280; u += nb) {
        if (u < 1024) pack_unit(u, Apos, Aneg, tid);
        else gemm1_unit(u - 1024, x, W_l1, b_l1, tid, smemf);
    }
    gsync();

    // P2: tcs1 (64) + bitstage1 (128) + list0 (32)
    for (int u = blockIdx.x; u < 224; u += nb) {
        if (u < 64) tcs1_unit(u, tid, smemf);
        else if (u < 192) bitstage_unit(u - 64, (const uint4*)g_lastT[0], (uint4*)g_lastT[1],
                                        g_U[0], g_U[1], g_pc + NN, tid, smemf);
        else list_unit(u - 192, g_U[0], g_pc, g_list[0], g_llen[0], tid);
    }
    gsync();

    // P3: agg1 (256) + bitstage2 (128) + list1 (32)
    for (int u = blockIdx.x; u < 416; u += nb) {
        if (u < 256) agg1_unit(u, W_g1, b_g1, W_l2, b_l2, tid, smemf);
        else if (u < 384) bitstage_unit(u - 256, (const uint4*)g_lastT[1], (uint4*)g_lastT[2],
                                        g_U[1], g_U[2], g_pc + 2*NN, tid, smemf);
        else list_unit(u - 384, g_U[1], g_pc + NN, g_list[1], g_llen[1], tid);
    }
    gsync();

    // P4: agg2 (512) + bitstage3 (128) + list2 (32)
    for (int u = blockIdx.x; u < 672; u += nb) {
        if (u < 512) agg64_unit(u, g_xb[0], g_tb[0], 62, W_g2, 62, b_g2,
                                g_pc + NN, g_list[1], g_llen[1], g_cs + 256,
                                1.0f, 1, W_l3, b_l3,
                                g_pc + 2*NN, g_tb[1], g_cs + 2*256,
                                g_xb[1], tid, smemf);
        else if (u < 640) bitstage_unit(u - 512, (const uint4*)g_lastT[2], (uint4*)g_lastT[3],
                                        g_U[2], g_U[3], g_pc + 3*NN, tid, smemf);
        else list_unit(u - 640, g_U[2], g_pc + 2*NN, g_list[2], g_llen[2], tid);
    }
    gsync();

    // P5: agg3 (512) + bitstage4 (128) + list3 (32)
    for (int u = blockIdx.x; u < 672; u += nb) {
        if (u < 512) agg64_unit(u, g_xb[1], g_tb[1], 64, W_g3, 64, b_g3,
                                g_pc + 2*NN, g_list[2], g_llen[2], g_cs + 2*256,
                                0.5f, 1, nullptr, nullptr,
                                g_pc + 3*NN, g_tb[2], g_cs + 3*256,
                                g_xb[2], tid, smemf);
        else if (u < 640) bitstage_unit(u - 512, (const uint4*)g_lastT[3], (uint4*)g_lastT[4],
                                        g_U[3], g_U[4], g_pc + 4*NN, tid, smemf);
        else list_unit(u - 640, g_U[3], g_pc + 3*NN, g_list[3], g_llen[3], tid);
    }
    gsync();

    // P6: agg4 (512) + bitstage5 (128) + list4 (32)
    for (int u = blockIdx.x; u < 672; u += nb) {
        if (u < 512) agg64_unit(u, g_xb[2], g_tb[2], 64, W_g4, 64, b_g4,
                                g_pc + 3*NN, g_list[3], g_llen[3], g_cs + 3*256,
                                0.5f, 1, nullptr, nullptr,
                                g_pc + 4*NN, g_tb[3], g_cs + 4*256,
                                g_xb[3], tid, smemf);
        else if (u < 640) bitstage_unit(u - 512, (const uint4*)g_lastT[4], (uint4*)g_lastT[5],
                                        g_U[4], g_U[5], g_pc + 5*NN, tid, smemf);
        else list_unit(u - 640, g_U[4], g_pc + 4*NN, g_list[4], g_llen[4], tid);
    }
    gsync();

    // P7: agg5 (512) + list5 (32)
    for (int u = blockIdx.x; u < 544; u += nb) {
        if (u < 512) agg64_unit(u, g_xb[3], g_tb[3], 64, W_g5, 64, b_g5,
                                g_pc + 4*NN, g_list[4], g_llen[4], g_cs + 4*256,
                                0.25f, 1, nullptr, nullptr,
                                g_pc + 5*NN, g_tb[4], g_cs + 5*256,
                                g_xb[4], tid, smemf);
        else list_unit(u - 512, g_U[5], g_pc + 5*NN, g_list[5], g_llen[5], tid);
    }
    gsync();

    // P8: agg6 (512, no relu) -> out
    for (int u = blockIdx.x; u < 512; u += nb)
        agg64_unit(u, g_xb[4], g_tb[4], 64, W_g6, 64, b_g6,
                   g_pc + 5*NN, g_list[5], g_llen[5], g_cs + 5*256,
                   0.25f, 0, nullptr, nullptr,
                   nullptr, nullptr, nullptr,
                   out, tid, smemf);
}

// ---------------- host ----------------
extern "C" void kernel_launch(void* const* d_in, const int* in_sizes, int n_in,
                              void* d_out, int out_size)
{
    const float* x    = (const float*)d_in[0];
    const float* Aneg = (const float*)d_in[1];
    const float* Apos = (const float*)d_in[2];
    const float* W_l1 = (const float*)d_in[3];  const float* b_l1 = (const float*)d_in[4];
    const float* W_l2 = (const float*)d_in[5];  const float* b_l2 = (const float*)d_in[6];
    const float* W_l3 = (const float*)d_in[7];  const float* b_l3 = (const float*)d_in[8];
    const float* W_g1 = (const float*)d_in[9];  const float* b_g1 = (const float*)d_in[10];
    const float* W_g2 = (const float*)d_in[11]; const float* b_g2 = (const float*)d_in[12];
    const float* W_g3 = (const float*)d_in[13]; const float* b_g3 = (const float*)d_in[14];
    const float* W_g4 = (const float*)d_in[15]; const float* b_g4 = (const float*)d_in[16];
    const float* W_g5 = (const float*)d_in[17]; const float* b_g5 = (const float*)d_in[18];
    const float* W_g6 = (const float*)d_in[19]; const float* b_g6 = (const float*)d_in[20];
    float* out = (float*)d_out;

    static int nblk = 0;
    if (!nblk) {
        int dev = 0, sms = 0, bpm = 0;
        cudaGetDevice(&dev);
        cudaDeviceGetAttribute(&sms, cudaDevAttrMultiProcessorCount, dev);
        cudaOccupancyMaxActiveBlocksPerMultiprocessor(&bpm, mega_kernel, NTHR, 0);
        if (sms <= 0) sms = 148;
        if (bpm <= 0) bpm = 2;
        if (bpm > 2) bpm = 2;
        nblk = sms * bpm;
    }

    mega_kernel<<<nblk, NTHR>>>(x, Aneg, Apos,
                                W_l1, b_l1, W_l2, b_l2, W_l3, b_l3,
                                W_g1, b_g1, W_g2, b_g2, W_g3, b_g3,
                                W_g4, b_g4, W_g5, b_g5, W_g6, b_g6,
                                out);
}

// round 14
// speedup vs baseline: 1.0632x; 1.0120x over previous
#include <cuda_runtime.h>
#include <stdint.h>

#define NN 2048
#define NW 64    // 2048 bits = 64 u32 words
#define CAP 128  // CSC capacity per column of A_pos
#define NTHR 256

// ---------------- device scratch ----------------
__device__ __align__(16) uint32_t g_apT[NN*NW];
__device__ unsigned short g_idx[NN*CAP];
__device__ int      g_cnt[NN];
__device__ __align__(16) uint32_t g_lastT[6][NN*NW];
__device__ __align__(16) uint32_t g_U[6][NN*NW];     // union bits per stage
__device__ int      g_pc[6*NN];
__device__ float    g_cs[6*256];
__device__ unsigned short g_list[6][NN*1024];        // per-row index lists (set or complement)
__device__ int      g_llen[6][NN];                   // len | (comp<<16)
__device__ __align__(16) float g_h1[NN*256];
__device__ __align__(16) float g_t1[NN*256];         // dinv0 .* h1
__device__ __align__(16) float g_xb[5][NN*64];       // h2, h3, x3, x4, x5
__device__ __align__(16) float g_tb[5][NN*64];       // t2..t6
__device__ int          g_barCount = 0;
__device__ volatile int g_barGen   = 0;

// ---------------- software grid barrier (atomic arrival — measured best) ----------------
__device__ __forceinline__ void gsync()
{
    __threadfence();
    __syncthreads();
    if (threadIdx.x == 0) {
        int gen = g_barGen;
        if (atomicAdd(&g_barCount, 1) == (int)gridDim.x - 1) {
            g_barCount = 0;
            __threadfence();
            g_barGen = gen + 1;
        } else {
            while (g_barGen == gen) { __nanosleep(32); }
        }
    }
    __syncthreads();
}

// ---------------- pack: [0,512) A_pos -> apT+CSC ; [512,1024) A_neg -> U0,lastT0,pc0 ----------------
__device__ void pack_unit(int u, const float* __restrict__ Apos, const float* __restrict__ Aneg, int tid)
{
    int lane = tid & 31;
    if (u < 512) {
        int gwarp = u*8 + (tid >> 5);
        int ti = gwarp >> 6, tj = gwarp & 63;
        uint32_t tbits = 0;
#pragma unroll
        for (int r = 0; r < 32; r++) {
            float v = Apos[(size_t)(ti*32 + r)*NN + tj*32 + lane];
            tbits |= (v > 0.f ? 1u : 0u) << r;
        }
        int j = tj*32 + lane;
        g_apT[j*NW + ti] = tbits;
        uint32_t m = tbits;
        while (m) {
            int r = __ffs(m) - 1; m &= (m-1);
            int pos = atomicAdd(&g_cnt[j], 1);
            if (pos < CAP) g_idx[j*CAP + pos] = (unsigned short)(ti*32 + r);
        }
    } else {
        int gwarp = (u - 512)*8 + (tid >> 5);
        int ti = gwarp >> 6, tj = gwarp & 63;
        uint32_t tbits = 0, rw = 0;
#pragma unroll
        for (int r = 0; r < 32; r++) {
            float v = Aneg[(size_t)(ti*32 + r)*NN + tj*32 + lane];
            uint32_t b = (v > 0.f) ? 1u : 0u;
            tbits |= b << r;
            uint32_t m = __ballot_sync(0xffffffffu, b);
            if (lane == r) rw = m;
        }
        g_U[0][(ti*32 + lane)*NW + tj] = rw;
        atomicAdd(&g_pc[ti*32 + lane], __popc(rw));
        g_lastT[0][(tj*32 + lane)*NW + ti] = tbits;
    }
}

// ---------------- bit stage: CSC expand + transpose + OR + pc ----------------
__device__ void bitstage_unit(int v, const uint4* __restrict__ lastOld4, uint4* __restrict__ lastNew4,
                              const uint32_t* __restrict__ uPrev, uint32_t* __restrict__ uCur,
                              int* __restrict__ pcCur, int tid, float* smemf)
{
    uint32_t (*sN)[33] = (uint32_t(*)[33])smemf;
    __syncthreads();
    int jt = v & 63, wt = v >> 6;
    int jl = tid >> 3, w4l = tid & 7;
    int j = jt*32 + jl;
    int w4 = wt*8 + w4l;

    int c = g_cnt[j]; if (c > CAP) c = CAP;
    const unsigned short* lst = g_idx + j*CAP;
    uint4 acc = make_uint4(0u,0u,0u,0u);
    int t = 0;
    for (; t + 4 <= c; t += 4) {
        int k0 = lst[t], k1 = lst[t+1], k2 = lst[t+2], k3 = lst[t+3];
        uint4 v0 = lastOld4[k0*16 + w4];
        uint4 v1 = lastOld4[k1*16 + w4];
        uint4 v2 = lastOld4[k2*16 + w4];
        uint4 v3 = lastOld4[k3*16 + w4];
        acc.x |= v0.x | v1.x | v2.x | v3.x;
        acc.y |= v0.y | v1.y | v2.y | v3.y;
        acc.z |= v0.z | v1.z | v2.z | v3.z;
        acc.w |= v0.w | v1.w | v2.w | v3.w;
    }
    for (; t < c; t++) {
        uint4 vv = lastOld4[lst[t]*16 + w4];
        acc.x |= vv.x; acc.y |= vv.y; acc.z |= vv.z; acc.w |= vv.w;
    }
    lastNew4[j*16 + w4] = acc;
    sN[jl][w4l*4 + 0] = acc.x;
    sN[jl][w4l*4 + 1] = acc.y;
    sN[jl][w4l*4 + 2] = acc.z;
    sN[jl][w4l*4 + 3] = acc.w;
    __syncthreads();

    int warp = tid >> 5, lane = tid & 31;
    for (int wl = warp; wl < 32; wl += 8) {
        uint32_t v2 = sN[lane][wl];
        uint32_t ow = 0;
#pragma unroll
        for (int ib = 0; ib < 32; ib++) {
            uint32_t mm = __ballot_sync(0xffffffffu, (v2 >> ib) & 1u);
            if (lane == ib) ow = mm;
        }
        int i = (wt*32 + wl)*32 + lane;
        uint32_t merged = uPrev[i*NW + jt] | ow;
        uCur[i*NW + jt] = merged;
        atomicAdd(&pcCur[i], __popc(merged));
    }
}

// ---------------- list build: per-row set-bit (or complement) index list ----------------
__device__ void list_unit(int u, const uint32_t* __restrict__ U, const int* __restrict__ pcS,
                          unsigned short* __restrict__ list, int* __restrict__ llen, int tid)
{
    int warp = tid >> 5, lane = tid & 31;
    for (int rr = 0; rr < 8; rr++) {
        int row = u*64 + warp*8 + rr;
        int pcv = pcS[row];
        bool comp = pcv > 1024;
        uint32_t m0 = U[row*NW + 2*lane];
        uint32_t m1 = U[row*NW + 2*lane + 1];
        if (comp) { m0 = ~m0; m1 = ~m1; }
        int cnt = __popc(m0) + __popc(m1);
        int incl = cnt;
#pragma unroll
        for (int off = 1; off < 32; off <<= 1) {
            int n = __shfl_up_sync(0xffffffffu, incl, off);
            if (lane >= off) incl += n;
        }
        int base = incl - cnt;
        unsigned short* dst = list + (size_t)row*1024 + base;
        int kb = lane*64;
        while (m0) { int b = __ffs(m0)-1; m0 &= (m0-1); *dst++ = (unsigned short)(kb + b); }
        kb += 32;
        while (m1) { int b = __ffs(m1)-1; m1 &= (m1-1); *dst++ = (unsigned short)(kb + b); }
        int total = __shfl_sync(0xffffffffu, incl, 31);
        if (lane == 31) llen[row] = total | (comp ? (1 << 16) : 0);
    }
}

// ---------------- gemm1: h1 = x @ W_l1 + b_l1 (32x64 tile, K-chunk 32) ----------------
__device__ void gemm1_unit(int u, const float* __restrict__ A, const float* __restrict__ W,
                           const float* __restrict__ bias, int tid, float* smemf)
{
    float (*As)[34] = (float(*)[34])smemf;             // 32x34
    float (*Ws)[64] = (float(*)[64])(smemf + 1088);    // 32x64
    __syncthreads();
    int tx = tid & 15, ty = tid >> 4;
    int rowBase = (u >> 2)*32, colBase = (u & 3)*64;
    float acc[2][4] = {};
    int mA = tid >> 3, kq = (tid & 7)*4;
    int kkW = tid >> 4, cW = (tid & 15)*4;

    for (int k0 = 0; k0 < 512; k0 += 32) {
        float4 a4 = *(const float4*)(A + (size_t)(rowBase + mA)*512 + k0 + kq);
        As[kq+0][mA] = a4.x; As[kq+1][mA] = a4.y;
        As[kq+2][mA] = a4.z; As[kq+3][mA] = a4.w;
        *(float4*)&Ws[kkW][cW]      = *(const float4*)(W + (size_t)(k0 + kkW)*256 + colBase + cW);
        *(float4*)&Ws[kkW+16][cW]   = *(const float4*)(W + (size_t)(k0 + kkW + 16)*256 + colBase + cW);
        __syncthreads();
#pragma unroll
        for (int kk = 0; kk < 32; kk++) {
            float2 av = *(const float2*)&As[kk][ty*2];
            float4 bv = *(const float4*)&Ws[kk][tx*4];
            acc[0][0] += av.x*bv.x; acc[0][1] += av.x*bv.y;
            acc[0][2] += av.x*bv.z; acc[0][3] += av.x*bv.w;
            acc[1][0] += av.y*bv.x; acc[1][1] += av.y*bv.y;
            acc[1][2] += av.y*bv.z; acc[1][3] += av.y*bv.w;
        }
        __syncthreads();
    }
#pragma unroll
    for (int a = 0; a < 2; a++) {
        int row = rowBase + ty*2 + a;
#pragma unroll
        for (int b = 0; b < 4; b++) {
            int col = colBase + tx*4 + b;
            g_h1[(size_t)row*256 + col] = acc[a][b] + bias[col];
        }
    }
}

// ---------------- t1 = dinv0 .* h1 ; cs0 colsum.  unit u in [0,64): 32 rows ----------------
__device__ void tcs1_unit(int u, int tid, float* smemf)
{
    float (*red)[256] = (float(*)[256])smemf;
    __syncthreads();
    int col4 = (tid & 63)*4;
    int rgrp = tid >> 6;
    int row0 = u*32;
    float s0=0.f, s1=0.f, s2=0.f, s3=0.f;
#pragma unroll
    for (int p = 0; p < 8; p++) {
        int row = row0 + rgrp*8 + p;
        float di = rsqrtf((float)(g_pc[row] + 1));
        float4 hv = *(const float4*)(g_h1 + (size_t)row*256 + col4);
        float4 tv = make_float4(di*hv.x, di*hv.y, di*hv.z, di*hv.w);
        *(float4*)(g_t1 + (size_t)row*256 + col4) = tv;
        s0 += tv.x; s1 += tv.y; s2 += tv.z; s3 += tv.w;
    }
    red[rgrp][col4+0] = s0; red[rgrp][col4+1] = s1;
    red[rgrp][col4+2] = s2; red[rgrp][col4+3] = s3;
    __syncthreads();
    atomicAdd(&g_cs[tid], red[0][tid]+red[1][tid]+red[2][tid]+red[3][tid]);
}

// ---------------- agg1: unit u in [0,256): 8 rows ----------------
__device__ void agg1_unit(int u, const float* __restrict__ Wg, const float* __restrict__ bg,
                          const float* __restrict__ Wl, const float* __restrict__ bl,
                          int tid, float* smemf)
{
    float (*sZ)[256] = (float(*)[256])smemf;            // 2048
    float (*sX)[256] = (float(*)[256])(smemf + 2048);   // 2048
    float (*red)[64] = (float(*)[64])(smemf + 4096);    // 512
    __syncthreads();
    int row0 = u*8;

    // phase A: z = di*(S + t1_row), S from list0 over t1 (unroll 4 for MLP)
    {
        int grp = tid >> 5, lane = tid & 31;
        int f = lane*8;
        int row = row0 + grp;
        int lv = g_llen[0][row];
        int len = lv & 0xFFFF;
        bool comp = (lv >> 16) != 0;
        const unsigned short* L = g_list[0] + (size_t)row*1024;
        float4 a0 = make_float4(0,0,0,0), a1 = make_float4(0,0,0,0);
        int t = 0;
        for (; t + 4 <= len; t += 4) {
            int k0 = L[t], k1 = L[t+1], k2 = L[t+2], k3 = L[t+3];
            float4 v00 = *(const float4*)(g_t1 + (size_t)k0*256 + f);
            float4 v01 = *(const float4*)(g_t1 + (size_t)k0*256 + f + 4);
            float4 v10 = *(const float4*)(g_t1 + (size_t)k1*256 + f);
            float4 v11 = *(const float4*)(g_t1 + (size_t)k1*256 + f + 4);
            float4 v20 = *(const float4*)(g_t1 + (size_t)k2*256 + f);
            float4 v21 = *(const float4*)(g_t1 + (size_t)k2*256 + f + 4);
            float4 v30 = *(const float4*)(g_t1 + (size_t)k3*256 + f);
            float4 v31 = *(const float4*)(g_t1 + (size_t)k3*256 + f + 4);
            a0.x += (v00.x + v10.x) + (v20.x + v30.x);
            a0.y += (v00.y + v10.y) + (v20.y + v30.y);
            a0.z += (v00.z + v10.z) + (v20.z + v30.z);
            a0.w += (v00.w + v10.w) + (v20.w + v30.w);
            a1.x += (v01.x + v11.x) + (v21.x + v31.x);
            a1.y += (v01.y + v11.y) + (v21.y + v31.y);
            a1.z += (v01.z + v11.z) + (v21.z + v31.z);
            a1.w += (v01.w + v11.w) + (v21.w + v31.w);
        }
        for (; t < len; t++) {
            int k0 = L[t];
            float4 v00 = *(const float4*)(g_t1 + (size_t)k0*256 + f);
            float4 v01 = *(const float4*)(g_t1 + (size_t)k0*256 + f + 4);
            a0.x += v00.x; a0.y += v00.y; a0.z += v00.z; a0.w += v00.w;
            a1.x += v01.x; a1.y += v01.y; a1.z += v01.z; a1.w += v01.w;
        }
        if (comp) {
            float4 c0 = *(const float4*)(g_cs + f);
            float4 c1 = *(const float4*)(g_cs + f + 4);
            a0.x = c0.x - a0.x; a0.y = c0.y - a0.y; a0.z = c0.z - a0.z; a0.w = c0.w - a0.w;
            a1.x = c1.x - a1.x; a1.y = c1.y - a1.y; a1.z = c1.z - a1.z; a1.w = c1.w - a1.w;
        }
        float di = rsqrtf((float)(g_pc[row] + 1));
        float4 t0 = *(const float4*)(g_t1 + (size_t)row*256 + f);
        float4 t1v = *(const float4*)(g_t1 + (size_t)row*256 + f + 4);
        sZ[grp][f+0] = di*(a0.x + t0.x); sZ[grp][f+1] = di*(a0.y + t0.y);
        sZ[grp][f+2] = di*(a0.z + t0.z); sZ[grp][f+3] = di*(a0.w + t0.w);
        sZ[grp][f+4] = di*(a1.x + t1v.x); sZ[grp][f+5] = di*(a1.y + t1v.y);
        sZ[grp][f+6] = di*(a1.z + t1v.z); sZ[grp][f+7] = di*(a1.w + t1v.w);
    }
    __syncthreads();

    // phase B: x1 = h1 + relu(z @ Wg + bg)
    {
        int col = tid;
        float a8[8] = {0,0,0,0,0,0,0,0};
        for (int k = 0; k < 256; k += 4) {
            float w0 = Wg[(size_t)(k+0)*256 + col];
            float w1 = Wg[(size_t)(k+1)*256 + col];
            float w2 = Wg[(size_t)(k+2)*256 + col];
            float w3 = Wg[(size_t)(k+3)*256 + col];
#pragma unroll
            for (int r = 0; r < 8; r++) {
                float4 zq = *(const float4*)&sZ[r][k];
                a8[r] += zq.x*w0 + zq.y*w1 + zq.z*w2 + zq.w*w3;
            }
        }
        float bv = bg[col];
#pragma unroll
        for (int r = 0; r < 8; r++)
            sX[r][col] = g_h1[(size_t)(row0 + r)*256 + col] + fmaxf(a8[r] + bv, 0.f);
    }
    __syncthreads();

    // phase C: h2 = x1 @ W_l2 + b_l2; t2 = dinv1*h2; cs1
    {
        int col = tid & 63;
        int rg = tid >> 6;
        float v0 = 0.f, v1 = 0.f;
        if (col < 62) {
            for (int k = 0; k < 256; k += 4) {
                float w0 = Wl[(size_t)(k+0)*62 + col];
                float w1 = Wl[(size_t)(k+1)*62 + col];
                float w2 = Wl[(size_t)(k+2)*62 + col];
                float w3 = Wl[(size_t)(k+3)*62 + col];
                float4 xa = *(const float4*)&sX[rg*2][k];
                float4 xb = *(const float4*)&sX[rg*2+1][k];
                v0 += xa.x*w0 + xa.y*w1 + xa.z*w2 + xa.w*w3;
                v1 += xb.x*w0 + xb.y*w1 + xb.z*w2 + xb.w*w3;
            }
            float bv = bl[col];
            v0 += bv; v1 += bv;
        }
        int rA = row0 + rg*2, rB = rA + 1;
        float dA = rsqrtf((float)(g_pc[NN + rA] + 1));
        float dB = rsqrtf((float)(g_pc[NN + rB] + 1));
        g_xb[0][(size_t)rA*64 + col] = v0;
        g_xb[0][(size_t)rB*64 + col] = v1;
        float tA = dA*v0, tB = dB*v1;
        g_tb[0][(size_t)rA*64 + col] = tA;
        g_tb[0][(size_t)rB*64 + col] = tB;
        red[rg*2][col] = tA;
        red[rg*2+1][col] = tB;
    }
    __syncthreads();
    if (tid < 64) {
        float s = 0.f;
#pragma unroll
        for (int r = 0; r < 8; r++) s += red[r][tid];
        atomicAdd(&g_cs[256 + tid], s);
    }
}

// ---------------- agg64 v3: 4 rows/unit, transposed smem W for float4 dot ----------------
__device__ void agg64_unit(int u,
        const float* __restrict__ h, const float* __restrict__ tArr, int NcIn,
        const float* __restrict__ Wg, int ldwg, const float* __restrict__ bg,
        const int* __restrict__ pcS,
        const unsigned short* __restrict__ lst, const int* __restrict__ llen,
        const float* __restrict__ cs,
        float wscale, int doRelu,
        const float* __restrict__ Wl, const float* __restrict__ bl,
        const int* __restrict__ pcNext, float* __restrict__ tNext, float* __restrict__ csNext,
        float* __restrict__ outp, int tid, float* smemf)
{
    float (*sWT)[68]    = (float(*)[68])smemf;               // [col][k], 64x68 = 4352 floats
    float (*sZp)[4][64] = (float(*)[4][64])(smemf + 4352);   // 1024
    float (*sY)[64]     = (float(*)[64])(smemf + 5376);      // 256
    float (*red)[64]    = (float(*)[64])(smemf + 5632);      // 256
    __syncthreads();
    int row0 = u*4;

    for (int t = tid; t < 64*64; t += NTHR) {
        int k = t >> 6, c = t & 63;
        sWT[c][k] = (k < NcIn && c < NcIn) ? Wg[(size_t)k*ldwg + c] : 0.f;
    }

    int r = tid >> 6;            // row within unit (0..3)
    int row = row0 + r;

    // phase A-1: slice partial sums.  64 threads/row = 4 slices x 16 lanes
    {
        int sl = (tid >> 4) & 3;
        int f = (tid & 15)*4;
        int lv = llen[row];
        int len = lv & 0xFFFF;
        const unsigned short* L = lst + (size_t)row*1024;
        int t0 = (len*sl) >> 2;
        int t1 = (len*(sl+1)) >> 2;
        float4 acc = make_float4(0,0,0,0);
        int t = t0;
        for (; t + 4 <= t1; t += 4) {
            int k0 = L[t], k1 = L[t+1], k2 = L[t+2], k3 = L[t+3];
            float4 a = *(const float4*)(tArr + (size_t)k0*64 + f);
            float4 b = *(const float4*)(tArr + (size_t)k1*64 + f);
            float4 c2 = *(const float4*)(tArr + (size_t)k2*64 + f);
            float4 d = *(const float4*)(tArr + (size_t)k3*64 + f);
            acc.x += (a.x + b.x) + (c2.x + d.x);
            acc.y += (a.y + b.y) + (c2.y + d.y);
            acc.z += (a.z + b.z) + (c2.z + d.z);
            acc.w += (a.w + b.w) + (c2.w + d.w);
        }
        for (; t < t1; t++) {
            float4 a = *(const float4*)(tArr + (size_t)L[t]*64 + f);
            acc.x += a.x; acc.y += a.y; acc.z += a.z; acc.w += a.w;
        }
        *(float4*)&sZp[r][sl][f] = acc;
    }
    __syncthreads();

    // phase A-2: combine slices + complement + dinv -> z (stored into sZp[r][0])
    int col = tid & 63;
    {
        float s = sZp[r][0][col] + sZp[r][1][col] + sZp[r][2][col] + sZp[r][3][col];
        bool comp = (llen[row] >> 16) != 0;
        if (comp) s = cs[col] - s;
        float di = rsqrtf((float)(pcS[row] + 1));
        float z = di*(s + tArr[(size_t)row*64 + col]);
        __syncthreads();
        sZp[r][0][col] = z;
    }
    __syncthreads();

    // phase B: y = h + wscale*act(z@Wg + bg), float4 dot via transposed W
    float y = 0.f;
#pragma unroll
    for (int k = 0; k < 64; k += 4) {
        float4 zv = *(const float4*)&sZp[r][0][k];
        float4 wv = *(const float4*)&sWT[col][k];
        y += zv.x*wv.x + zv.y*wv.y + zv.z*wv.z + zv.w*wv.w;
    }
    {
        float b = (col < NcIn) ? bg[col] : 0.f;
        float v = y + b;
        if (doRelu) v = fmaxf(v, 0.f);
        y = h[(size_t)row*64 + col] + wscale*v;
    }

    float val;
    if (Wl) {
        sY[r][col] = y;
        __syncthreads();
        for (int t = tid; t < 64*64; t += NTHR) {
            int k = t >> 6, c2 = t & 63;
            sWT[c2][k] = (k < NcIn) ? Wl[(size_t)k*64 + c2] : 0.f;
        }
        __syncthreads();
        val = 0.f;
#pragma unroll
        for (int k = 0; k < 64; k += 4) {
            float4 yv = *(const float4*)&sY[r][k];
            float4 wv = *(const float4*)&sWT[col][k];
            val += yv.x*wv.x + yv.y*wv.y + yv.z*wv.z + yv.w*wv.w;
        }
        val += bl[col];
    } else {
        val = y;
    }

    outp[(size_t)row*64 + col] = val;

    if (csNext) {
        float dN = rsqrtf((float)(pcNext[row] + 1));
        float tv = dN*val;
        tNext[(size_t)row*64 + col] = tv;
        red[r][col] = tv;
        __syncthreads();
        if (tid < 64)
            atomicAdd(&csNext[tid], red[0][tid]+red[1][tid]+red[2][tid]+red[3][tid]);
    }
}

// ---------------- the mega kernel ----------------
__global__ void __launch_bounds__(NTHR, 2) mega_kernel(
        const float* __restrict__ x, const float* __restrict__ Aneg, const float* __restrict__ Apos,
        const float* __restrict__ W_l1, const float* __restrict__ b_l1,
        const float* __restrict__ W_l2, const float* __restrict__ b_l2,
        const float* __restrict__ W_l3, const float* __restrict__ b_l3,
        const float* __restrict__ W_g1, const float* __restrict__ b_g1,
        const float* __restrict__ W_g2, const float* __restrict__ b_g2,
        const float* __restrict__ W_g3, const float* __restrict__ b_g3,
        const float* __restrict__ W_g4, const float* __restrict__ b_g4,
        const float* __restrict__ W_g5, const float* __restrict__ b_g5,
        const float* __restrict__ W_g6, const float* __restrict__ b_g6,
        float* __restrict__ out)
{
    __shared__ __align__(16) float smemf[6144];   // 24 KB
    int tid = threadIdx.x;
    int nb = gridDim.x;

    // P0: zero
    for (int i = blockIdx.x*NTHR + tid; i < 6*NN;  i += nb*NTHR) g_pc[i] = 0;
    for (int i = blockIdx.x*NTHR + tid; i < 6*256; i += nb*NTHR) g_cs[i] = 0.f;
    for (int i = blockIdx.x*NTHR + tid; i < NN;    i += nb*NTHR) g_cnt[i] = 0;
    gsync();

    // P1: pack (1024) + gemm1 (256)
    for (int u = blockIdx.x; u < 1280; u += nb) {
        if (u < 1024) pack_unit(u, Apos, Aneg, tid);
        else gemm1_unit(u - 1024, x, W_l1, b_l1, tid, smemf);
    }
    gsync();

    // P2: tcs1 (64) + bitstage1 (128) + list0 (32)
    for (int u = blockIdx.x; u < 224; u += nb) {
        if (u < 64) tcs1_unit(u, tid, smemf);
        else if (u < 192) bitstage_unit(u - 64, (const uint4*)g_lastT[0], (uint4*)g_lastT[1],
                                        g_U[0], g_U[1], g_pc + NN, tid, smemf);
        else list_unit(u - 192, g_U[0], g_pc, g_list[0], g_llen[0], tid);
    }
    gsync();

    // P3: agg1 (256) + bitstage2 (128) + list1 (32)
    for (int u = blockIdx.x; u < 416; u += nb) {
        if (u < 256) agg1_unit(u, W_g1, b_g1, W_l2, b_l2, tid, smemf);
        else if (u < 384) bitstage_unit(u - 256, (const uint4*)g_lastT[1], (uint4*)g_lastT[2],
                                        g_U[1], g_U[2], g_pc + 2*NN, tid, smemf);
        else list_unit(u - 384, g_U[1], g_pc + NN, g_list[1], g_llen[1], tid);
    }
    gsync();

    // P4: agg2 (512) + bitstage3 (128) + list2 (32)
    for (int u = blockIdx.x; u < 672; u += nb) {
        if (u < 512) agg64_unit(u, g_xb[0], g_tb[0], 62, W_g2, 62, b_g2,
                                g_pc + NN, g_list[1], g_llen[1], g_cs + 256,
                                1.0f, 1, W_l3, b_l3,
                                g_pc + 2*NN, g_tb[1], g_cs + 2*256,
                                g_xb[1], tid, smemf);
        else if (u < 640) bitstage_unit(u - 512, (const uint4*)g_lastT[2], (uint4*)g_lastT[3],
                                        g_U[2], g_U[3], g_pc + 3*NN, tid, smemf);
        else list_unit(u - 640, g_U[2], g_pc + 2*NN, g_list[2], g_llen[2], tid);
    }
    gsync();

    // P5: agg3 (512) + bitstage4 (128) + list3 (32)
    for (int u = blockIdx.x; u < 672; u += nb) {
        if (u < 512) agg64_unit(u, g_xb[1], g_tb[1], 64, W_g3, 64, b_g3,
                                g_pc + 2*NN, g_list[2], g_llen[2], g_cs + 2*256,
                                0.5f, 1, nullptr, nullptr,
                                g_pc + 3*NN, g_tb[2], g_cs + 3*256,
                                g_xb[2], tid, smemf);
        else if (u < 640) bitstage_unit(u - 512, (const uint4*)g_lastT[3], (uint4*)g_lastT[4],
                                        g_U[3], g_U[4], g_pc + 4*NN, tid, smemf);
        else list_unit(u - 640, g_U[3], g_pc + 3*NN, g_list[3], g_llen[3], tid);
    }
    gsync();

    // P6: agg4 (512) + bitstage5 (128) + list4 (32)
    for (int u = blockIdx.x; u < 672; u += nb) {
        if (u < 512) agg64_unit(u, g_xb[2], g_tb[2], 64, W_g4, 64, b_g4,
                                g_pc + 3*NN, g_list[3], g_llen[3], g_cs + 3*256,
                                0.5f, 1, nullptr, nullptr,
                                g_pc + 4*NN, g_tb[3], g_cs + 4*256,
                                g_xb[3], tid, smemf);
        else if (u < 640) bitstage_unit(u - 512, (const uint4*)g_lastT[4], (uint4*)g_lastT[5],
                                        g_U[4], g_U[5], g_pc + 5*NN, tid, smemf);
        else list_unit(u - 640, g_U[4], g_pc + 4*NN, g_list[4], g_llen[4], tid);
    }
    gsync();

    // P7: agg5 (512) + list5 (32)
    for (int u = blockIdx.x; u < 544; u += nb) {
        if (u < 512) agg64_unit(u, g_xb[3], g_tb[3], 64, W_g5, 64, b_g5,
                                g_pc + 4*NN, g_list[4], g_llen[4], g_cs + 4*256,
                                0.25f, 1, nullptr, nullptr,
                                g_pc + 5*NN, g_tb[4], g_cs + 5*256,
                                g_xb[4], tid, smemf);
        else list_unit(u - 512, g_U[5], g_pc + 5*NN, g_list[5], g_llen[5], tid);
    }
    gsync();

    // P8: agg6 (512, no relu) -> out
    for (int u = blockIdx.x; u < 512; u += nb)
        agg64_unit(u, g_xb[4], g_tb[4], 64, W_g6, 64, b_g6,
                   g_pc + 5*NN, g_list[5], g_llen[5], g_cs + 5*256,
                   0.25f, 0, nullptr, nullptr,
                   nullptr, nullptr, nullptr,
                   out, tid, smemf);
}

// ---------------- host ----------------
extern "C" void kernel_launch(void* const* d_in, const int* in_sizes, int n_in,
                              void* d_out, int out_size)
{
    const float* x    = (const float*)d_in[0];
    const float* Aneg = (const float*)d_in[1];
    const float* Apos = (const float*)d_in[2];
    const float* W_l1 = (const float*)d_in[3];  const float* b_l1 = (const float*)d_in[4];
    const float* W_l2 = (const float*)d_in[5];  const float* b_l2 = (const float*)d_in[6];
    const float* W_l3 = (const float*)d_in[7];  const float* b_l3 = (const float*)d_in[8];
    const float* W_g1 = (const float*)d_in[9];  const float* b_g1 = (const float*)d_in[10];
    const float* W_g2 = (const float*)d_in[11]; const float* b_g2 = (const float*)d_in[12];
    const float* W_g3 = (const float*)d_in[13]; const float* b_g3 = (const float*)d_in[14];
    const float* W_g4 = (const float*)d_in[15]; const float* b_g4 = (const float*)d_in[16];
    const float* W_g5 = (const float*)d_in[17]; const float* b_g5 = (const float*)d_in[18];
    const float* W_g6 = (const float*)d_in[19]; const float* b_g6 = (const float*)d_in[20];
    float* out = (float*)d_out;

    static int nblk = 0;
    if (!nblk) {
        int dev = 0, sms = 0, bpm = 0;
        cudaGetDevice(&dev);
        cudaDeviceGetAttribute(&sms, cudaDevAttrMultiProcessorCount, dev);
        cudaOccupancyMaxActiveBlocksPerMultiprocessor(&bpm, mega_kernel, NTHR, 0);
        if (sms <= 0) sms = 148;
        if (bpm <= 0) bpm = 2;
        if (bpm > 2) bpm = 2;
        nblk = sms * bpm;
    }

    mega_kernel<<<nblk, NTHR>>>(x, Aneg, Apos,
                                W_l1, b_l1, W_l2, b_l2, W_l3, b_l3,
                                W_g1, b_g1, W_g2, b_g2, W_g3, b_g3,
                                W_g4, b_g4, W_g5, b_g5, W_g6, b_g6,
                                out);
}